// round 13
// baseline (speedup 1.0000x reference)
#include <cuda_runtime.h>
#include <cuda_fp16.h>
#include <cstdint>

// ---------------------------------------------------------------------------
// HydraAttention: B=8, L=4096, dim=1024, n_heads=8, d_head=128, d=16
// Round 13: fp16 pre-split + pure cp.async GEMM (no staging regs, 4 stages)
// ---------------------------------------------------------------------------

static constexpr int Bb  = 8;
static constexpr int Ll  = 4096;
static constexpr int DIM = 1024;
static constexpr int DH  = 128;
static constexpr int NH  = 8;
static constexpr int Dd  = 16;
static constexpr int MTOK = Bb * Ll;      // 32768

__device__ float g_qkv[3][MTOK * DH];     // 48 MB scratch
__device__ float g_kvpart[Bb * NH][16][Dd];
__device__ __align__(16) __half g_xf16[(size_t)MTOK * DIM];   // 64 MB
__device__ __align__(16) __half g_wf16[3 * DH * DIM];         // 0.75 MB (QKV cat)

// ---------------- PTX helpers ----------------------------------------------
__device__ __forceinline__ uint32_t smem_u32(const void* p) {
    uint32_t a;
    asm("{ .reg .u64 t; cvta.to.shared.u64 t, %1; cvt.u32.u64 %0, t; }"
        : "=r"(a) : "l"(p));
    return a;
}
__device__ __forceinline__ void cpasync16(uint32_t dst, const void* src) {
    asm volatile("cp.async.cg.shared.global [%0], [%1], 16;" :: "r"(dst), "l"(src));
}
__device__ __forceinline__ void ldsm4(uint32_t* r, uint32_t a) {
    asm volatile("ldmatrix.sync.aligned.m8n8.x4.shared.b16 {%0,%1,%2,%3}, [%4];"
        : "=r"(r[0]), "=r"(r[1]), "=r"(r[2]), "=r"(r[3]) : "r"(a));
}
__device__ __forceinline__ void mma_f16(float* c, const uint32_t* a, const uint32_t* b) {
    asm volatile(
        "mma.sync.aligned.m16n8k16.row.col.f32.f16.f16.f32 "
        "{%0,%1,%2,%3}, {%4,%5,%6,%7}, {%8,%9}, {%0,%1,%2,%3};"
        : "+f"(c[0]), "+f"(c[1]), "+f"(c[2]), "+f"(c[3])
        : "r"(a[0]), "r"(a[1]), "r"(a[2]), "r"(a[3]), "r"(b[0]), "r"(b[1]));
}

// Conflict-free swizzle for 64B rows.
__device__ __forceinline__ uint32_t swz(int row, int c16) {
    return (uint32_t)(row * 64 + ((c16 ^ ((row >> 1) & 3)) << 4));
}

// ---------------- Kernel 0a: X fp32 -> fp16 --------------------------------
__global__ __launch_bounds__(256) void split_x(const float* __restrict__ X) {
    const size_t t = (size_t)blockIdx.x * 256 + threadIdx.x;   // 8 elems each
    const float4* p = (const float4*)(X + t * 8);
    float4 a = p[0], b = p[1];
    __align__(16) __half h[8];
    h[0] = __float2half_rn(a.x); h[1] = __float2half_rn(a.y);
    h[2] = __float2half_rn(a.z); h[3] = __float2half_rn(a.w);
    h[4] = __float2half_rn(b.x); h[5] = __float2half_rn(b.y);
    h[6] = __float2half_rn(b.z); h[7] = __float2half_rn(b.w);
    *(uint4*)(g_xf16 + t * 8) = *(const uint4*)h;
}

// ---------------- Kernel 0b: W fp32 -> fp16 (QKV concatenated) -------------
__global__ __launch_bounds__(256) void split_w(const float* __restrict__ Wq,
                                               const float* __restrict__ Wk,
                                               const float* __restrict__ Wv) {
    const size_t t = (size_t)blockIdx.x * 256 + threadIdx.x;
    const size_t e = t * 8;                      // 0..393215
    const int mat = (int)(e >> 17);              // 131072 elems per matrix
    const size_t off = e & 131071;
    const float* W = (mat == 0) ? Wq : (mat == 1) ? Wk : Wv;
    const float4* p = (const float4*)(W + off);
    float4 a = p[0], b = p[1];
    __align__(16) __half h[8];
    h[0] = __float2half_rn(a.x); h[1] = __float2half_rn(a.y);
    h[2] = __float2half_rn(a.z); h[3] = __float2half_rn(a.w);
    h[4] = __float2half_rn(b.x); h[5] = __float2half_rn(b.y);
    h[6] = __float2half_rn(b.z); h[7] = __float2half_rn(b.w);
    *(uint4*)(g_wf16 + e) = *(const uint4*)h;
}

// ---------------- Kernel 1: cp.async fp16 QKV GEMM -------------------------
// grid = (2, 256): N-half x M-block. Stage (20KB):
//   A[128x32] @0 (8KB), B[192x32] @8192 (12KB); 4 stages = 80KB
static constexpr uint32_t STAGE = 20480;
static constexpr int NSTG = 4;
static constexpr uint32_t GEMM_SMEM = NSTG * STAGE;   // 81920
static constexpr int NCH = 32;
static constexpr int NTHR = 512;

__global__ __launch_bounds__(NTHR, 1) void qkv_gemm(
    const float* __restrict__ bq, const float* __restrict__ bk,
    const float* __restrict__ bv)
{
    extern __shared__ __align__(128) unsigned char smem[];
    const uint32_t sbase = smem_u32(smem);
    const int tid = threadIdx.x, lid = tid & 31, wid = tid >> 5;
    const int nb = blockIdx.x;            // 0/1 -> QKV cols [nb*192, +192)
    const int bm = blockIdx.y * 128;
    const int wm = (wid >> 2) * 32;       // 4 M-warps
    const int wn = (wid & 3) * 48;        // 4 N-warps

    float acc[2][6][4];
#pragma unroll
    for (int i = 0; i < 2; i++)
#pragma unroll
        for (int j = 0; j < 6; j++)
#pragma unroll
            for (int k = 0; k < 4; k++) acc[i][j][k] = 0.f;

    // A: 128 rows x 4 slots = 512 -> 1/thread. B: 768 slots -> 1 + (tid<256).
    const int arow = tid >> 2, ac16 = tid & 3;
    const __half* Asrc = g_xf16 + (size_t)(bm + arow) * DIM + ac16 * 8;
    const int brow0 = tid >> 2;
    const __half* Bsrc0 = g_wf16 + (size_t)(nb * 192 + brow0) * DIM + ac16 * 8;
    const int brow1 = (tid + NTHR) >> 2;
    const __half* Bsrc1 = g_wf16 + (size_t)(nb * 192 + brow1) * DIM + ac16 * 8;
    const uint32_t adst = swz(arow, ac16);
    const uint32_t bdst0 = 8192 + swz(brow0, ac16);
    const uint32_t bdst1 = 8192 + swz(brow1, ac16);

    auto issue_stage = [&](int kc, int s) {
        const uint32_t st = sbase + (uint32_t)s * STAGE;
        const size_t ko = (size_t)kc * 32;
        cpasync16(st + adst, Asrc + ko);
        cpasync16(st + bdst0, Bsrc0 + ko);
        if (tid < 256) cpasync16(st + bdst1, Bsrc1 + ko);
        asm volatile("cp.async.commit_group;" ::: "memory");
    };

    issue_stage(0, 0);
    issue_stage(1, 1);
    issue_stage(2, 2);

    for (int c = 0; c < NCH; c++) {
        asm volatile("cp.async.wait_group 2;" ::: "memory");
        __syncthreads();
        if (c + 3 < NCH) issue_stage(c + 3, (c + 3) & 3);

        const uint32_t st = sbase + (uint32_t)(c & 3) * STAGE;
#pragma unroll
        for (int ks = 0; ks < 2; ks++) {
            uint32_t ah[8], bb[12];
#pragma unroll
            for (int mt = 0; mt < 2; mt++) {
                const int row = wm + mt * 16 + (lid & 15);
                const int c16 = ks * 2 + (lid >> 4);
                ldsm4(ah + mt * 4, st + swz(row, c16));
            }
#pragma unroll
            for (int np = 0; np < 3; np++) {
                const int row = wn + np * 16 + (lid & 7) + ((lid >> 4) << 3);
                const int c16 = ks * 2 + ((lid >> 3) & 1);
                ldsm4(bb + np * 4, st + 8192 + swz(row, c16));
            }
#pragma unroll
            for (int mt = 0; mt < 2; mt++)
#pragma unroll
                for (int np = 0; np < 3; np++) {
                    mma_f16(acc[mt][np*2],     ah + mt*4, bb + np*4);
                    mma_f16(acc[mt][np*2 + 1], ah + mt*4, bb + np*4 + 2);
                }
        }
        __syncthreads();   // LDSM of stage c done before it is refilled
    }

    // epilogue: add bias, store fp32 into g_qkv[mat]
    const int tr = lid >> 2, tc = (lid & 3) * 2;
#pragma unroll
    for (int mt = 0; mt < 2; mt++)
#pragma unroll
        for (int n8 = 0; n8 < 6; n8++) {
            const int gn  = nb * 192 + wn + n8 * 8 + tc;
            const int mat = gn >> 7;
            const int col = gn & 127;
            const float* bias = (mat == 0) ? bq : (mat == 1) ? bk : bv;
            float* Cp = g_qkv[mat];
            const float b0 = bias[col], b1 = bias[col + 1];
            const int r0 = bm + wm + mt * 16 + tr;
            float2 v0 = {acc[mt][n8][0] + b0, acc[mt][n8][1] + b1};
            float2 v1 = {acc[mt][n8][2] + b0, acc[mt][n8][3] + b1};
            *(float2*)&Cp[(size_t)r0 * DH + col]       = v0;
            *(float2*)&Cp[(size_t)(r0 + 8) * DH + col] = v1;
        }
}

// ---------------- Kernel 2: kv partial reduction (16 chunks) ---------------
__global__ __launch_bounds__(256) void kv_reduce() {
    const int bh    = blockIdx.x;     // 0..63
    const int chunk = blockIdx.y;     // 0..15
    const int b = bh >> 3, h = bh & 7;
    const float* __restrict__ K = g_qkv[1];
    const float* __restrict__ V = g_qkv[2];

    const int l = chunk * 256 + threadIdx.x;
    const size_t base = (size_t)(b * Ll + l) * DH + h * Dd;
    float kx[Dd], vx[Dd], acc[Dd];
    const float4* kp = (const float4*)(K + base);
    const float4* vp = (const float4*)(V + base);
#pragma unroll
    for (int q = 0; q < 4; q++) {
        float4 kv4 = kp[q];
        kx[q*4+0] = kv4.x; kx[q*4+1] = kv4.y; kx[q*4+2] = kv4.z; kx[q*4+3] = kv4.w;
        float4 vv4 = vp[q];
        vx[q*4+0] = vv4.x; vx[q*4+1] = vv4.y; vx[q*4+2] = vv4.z; vx[q*4+3] = vv4.w;
    }
    float ss = 0.f;
#pragma unroll
    for (int d = 0; d < Dd; d++) ss += kx[d] * kx[d];
    const float rn = rsqrtf(ss);
#pragma unroll
    for (int d = 0; d < Dd; d++) acc[d] = kx[d] * rn * vx[d];

    __shared__ float red[256][17];
#pragma unroll
    for (int d = 0; d < Dd; d++) red[threadIdx.x][d] = acc[d];
    __syncthreads();
    for (int s = 128; s > 0; s >>= 1) {
        if (threadIdx.x < s) {
#pragma unroll
            for (int d = 0; d < Dd; d++)
                red[threadIdx.x][d] += red[threadIdx.x + s][d];
        }
        __syncthreads();
    }
    if (threadIdx.x < Dd)
        g_kvpart[bh][chunk][threadIdx.x] = red[0][threadIdx.x];
}

// ---------------- Kernel 3: q-normalize * kv, LayerNorm --------------------
__global__ __launch_bounds__(256) void finalize(
    const float* __restrict__ gamma, const float* __restrict__ beta,
    float* __restrict__ out)
{
    const int idx = blockIdx.x * blockDim.x + threadIdx.x;
    const int l = idx & (Ll - 1);
    const int h = (idx >> 12) & 7;
    const int b = idx >> 15;

    const size_t qbase = (size_t)(b * Ll + l) * DH + h * Dd;
    float q[Dd];
    const float4* qp = (const float4*)(g_qkv[0] + qbase);
#pragma unroll
    for (int g = 0; g < 4; g++) {
        float4 v = qp[g];
        q[g*4+0] = v.x; q[g*4+1] = v.y; q[g*4+2] = v.z; q[g*4+3] = v.w;
    }

    const int bh = (b << 3) | h;
    float kv[Dd];
#pragma unroll
    for (int d = 0; d < Dd; d++) kv[d] = 0.f;
#pragma unroll
    for (int c = 0; c < 16; c++)
#pragma unroll
        for (int d = 0; d < Dd; d++) kv[d] += g_kvpart[bh][c][d];

    float ss = 0.f;
#pragma unroll
    for (int d = 0; d < Dd; d++) ss += q[d] * q[d];
    const float rn = rsqrtf(ss);

    float a[Dd];
    float mu = 0.f;
#pragma unroll
    for (int d = 0; d < Dd; d++) { a[d] = q[d] * rn * kv[d]; mu += a[d]; }
    mu *= (1.f / Dd);
    float var = 0.f;
#pragma unroll
    for (int d = 0; d < Dd; d++) { float t = a[d] - mu; var += t * t; }
    var *= (1.f / Dd);
    const float rs = rsqrtf(var + 1e-5f);

    float* op = out + (size_t)idx * Dd;
#pragma unroll
    for (int g = 0; g < 4; g++) {
        float4 o;
        o.x = (a[g*4+0] - mu) * rs * gamma[g*4+0] + beta[g*4+0];
        o.y = (a[g*4+1] - mu) * rs * gamma[g*4+1] + beta[g*4+1];
        o.z = (a[g*4+2] - mu) * rs * gamma[g*4+2] + beta[g*4+2];
        o.w = (a[g*4+3] - mu) * rs * gamma[g*4+3] + beta[g*4+3];
        *(float4*)&op[g * 4] = o;
    }
}

// ---------------------------------------------------------------------------
extern "C" void kernel_launch(void* const* d_in, const int* in_sizes, int n_in,
                              void* d_out, int out_size)
{
    (void)in_sizes; (void)n_in; (void)out_size;
    const float* x     = (const float*)d_in[0];
    const float* Wq    = (const float*)d_in[1];
    const float* bq    = (const float*)d_in[2];
    const float* Wk    = (const float*)d_in[3];
    const float* bk    = (const float*)d_in[4];
    const float* Wv    = (const float*)d_in[5];
    const float* bv    = (const float*)d_in[6];
    const float* gamma = (const float*)d_in[7];
    const float* beta  = (const float*)d_in[8];
    float* out = (float*)d_out;

    static bool attr_set = false;
    if (!attr_set) {
        cudaFuncSetAttribute(qkv_gemm,
                             cudaFuncAttributeMaxDynamicSharedMemorySize, GEMM_SMEM);
        attr_set = true;
    }

    split_x<<<16384, 256>>>(x);
    split_w<<<192, 256>>>(Wq, Wk, Wv);
    qkv_gemm<<<dim3(2, 256), NTHR, GEMM_SMEM>>>(bq, bk, bv);
    kv_reduce<<<dim3(Bb * NH, 16), 256>>>();
    finalize<<<(Bb * NH * Ll) / 256, 256>>>(gamma, beta, out);
}

// round 14
// speedup vs baseline: 1.1685x; 1.1685x over previous
#include <cuda_runtime.h>
#include <cuda_fp16.h>
#include <cstdint>

// ---------------------------------------------------------------------------
// HydraAttention: B=8, L=4096, dim=1024, n_heads=8, d_head=128, d=16
// Round 14: fp16 pre-split + cp.async GEMM with 2 CTAs/SM
//   (256 thr, CTA tile 64x192, 4 stages x 16KB, <=128 regs -> occupancy 2:
//    two independent barrier domains per SM cover sync/LDSM latency)
// ---------------------------------------------------------------------------

static constexpr int Bb  = 8;
static constexpr int Ll  = 4096;
static constexpr int DIM = 1024;
static constexpr int DH  = 128;
static constexpr int NH  = 8;
static constexpr int Dd  = 16;
static constexpr int MTOK = Bb * Ll;      // 32768

__device__ float g_qkv[3][MTOK * DH];     // 48 MB scratch
__device__ float g_kvpart[Bb * NH][16][Dd];
__device__ __align__(16) __half g_xf16[(size_t)MTOK * DIM];   // 64 MB
__device__ __align__(16) __half g_wf16[3 * DH * DIM];         // QKV concat

// ---------------- PTX helpers ----------------------------------------------
__device__ __forceinline__ uint32_t smem_u32(const void* p) {
    uint32_t a;
    asm("{ .reg .u64 t; cvta.to.shared.u64 t, %1; cvt.u32.u64 %0, t; }"
        : "=r"(a) : "l"(p));
    return a;
}
__device__ __forceinline__ void cpasync16(uint32_t dst, const void* src) {
    asm volatile("cp.async.cg.shared.global [%0], [%1], 16;" :: "r"(dst), "l"(src));
}
__device__ __forceinline__ void ldsm4(uint32_t* r, uint32_t a) {
    asm volatile("ldmatrix.sync.aligned.m8n8.x4.shared.b16 {%0,%1,%2,%3}, [%4];"
        : "=r"(r[0]), "=r"(r[1]), "=r"(r[2]), "=r"(r[3]) : "r"(a));
}
__device__ __forceinline__ void mma_f16(float* c, const uint32_t* a, const uint32_t* b) {
    asm volatile(
        "mma.sync.aligned.m16n8k16.row.col.f32.f16.f16.f32 "
        "{%0,%1,%2,%3}, {%4,%5,%6,%7}, {%8,%9}, {%0,%1,%2,%3};"
        : "+f"(c[0]), "+f"(c[1]), "+f"(c[2]), "+f"(c[3])
        : "r"(a[0]), "r"(a[1]), "r"(a[2]), "r"(a[3]), "r"(b[0]), "r"(b[1]));
}

// Conflict-free swizzle for 64B rows.
__device__ __forceinline__ uint32_t swz(int row, int c16) {
    return (uint32_t)(row * 64 + ((c16 ^ ((row >> 1) & 3)) << 4));
}

// ---------------- Kernel 0a: X fp32 -> fp16 --------------------------------
__global__ __launch_bounds__(256) void split_x(const float* __restrict__ X) {
    const size_t t = (size_t)blockIdx.x * 256 + threadIdx.x;   // 8 elems each
    const float4* p = (const float4*)(X + t * 8);
    float4 a = p[0], b = p[1];
    __align__(16) __half h[8];
    h[0] = __float2half_rn(a.x); h[1] = __float2half_rn(a.y);
    h[2] = __float2half_rn(a.z); h[3] = __float2half_rn(a.w);
    h[4] = __float2half_rn(b.x); h[5] = __float2half_rn(b.y);
    h[6] = __float2half_rn(b.z); h[7] = __float2half_rn(b.w);
    *(uint4*)(g_xf16 + t * 8) = *(const uint4*)h;
}

// ---------------- Kernel 0b: W fp32 -> fp16 (QKV concatenated) -------------
__global__ __launch_bounds__(256) void split_w(const float* __restrict__ Wq,
                                               const float* __restrict__ Wk,
                                               const float* __restrict__ Wv) {
    const size_t t = (size_t)blockIdx.x * 256 + threadIdx.x;
    const size_t e = t * 8;
    const int mat = (int)(e >> 17);
    const size_t off = e & 131071;
    const float* W = (mat == 0) ? Wq : (mat == 1) ? Wk : Wv;
    const float4* p = (const float4*)(W + off);
    float4 a = p[0], b = p[1];
    __align__(16) __half h[8];
    h[0] = __float2half_rn(a.x); h[1] = __float2half_rn(a.y);
    h[2] = __float2half_rn(a.z); h[3] = __float2half_rn(a.w);
    h[4] = __float2half_rn(b.x); h[5] = __float2half_rn(b.y);
    h[6] = __float2half_rn(b.z); h[7] = __float2half_rn(b.w);
    *(uint4*)(g_wf16 + e) = *(const uint4*)h;
}

// ---------------- Kernel 1: cp.async fp16 QKV GEMM, 2 CTAs/SM --------------
// grid = (2, 512): N-half x M-block(64). Stage (16KB):
//   A[64x32] @0 (4KB), B[192x32] @4096 (12KB); 4 stages = 64KB
static constexpr uint32_t STAGE = 16384;
static constexpr int NSTG = 4;
static constexpr uint32_t GEMM_SMEM = NSTG * STAGE;   // 65536
static constexpr int NCH = 32;
static constexpr int NTHR = 256;

__global__ __launch_bounds__(NTHR, 2) void qkv_gemm(
    const float* __restrict__ bq, const float* __restrict__ bk,
    const float* __restrict__ bv)
{
    extern __shared__ __align__(128) unsigned char smem[];
    const uint32_t sbase = smem_u32(smem);
    const int tid = threadIdx.x, lid = tid & 31, wid = tid >> 5;
    const int nb = blockIdx.x;            // 0/1 -> QKV cols [nb*192, +192)
    const int bm = blockIdx.y * 64;
    const int wm = (wid >> 2) * 32;       // 2 M-warps x 32
    const int wn = (wid & 3) * 48;        // 4 N-warps x 48

    float acc[2][6][4];
#pragma unroll
    for (int i = 0; i < 2; i++)
#pragma unroll
        for (int j = 0; j < 6; j++)
#pragma unroll
            for (int k = 0; k < 4; k++) acc[i][j][k] = 0.f;

    // A: 64 rows x 4 slots = 256 -> 1/thread. B: 768 slots -> 3/thread.
    const int arow = tid >> 2, ac16 = tid & 3;
    const __half* Asrc = g_xf16 + (size_t)(bm + arow) * DIM + ac16 * 8;
    const __half* Bs[3];
    uint32_t bdst[3];
#pragma unroll
    for (int u = 0; u < 3; u++) {
        const int id = tid + NTHR * u;
        const int row = id >> 2, c16 = id & 3;
        Bs[u] = g_wf16 + (size_t)(nb * 192 + row) * DIM + c16 * 8;
        bdst[u] = 4096 + swz(row, c16);
    }
    const uint32_t adst = swz(arow, ac16);

    auto issue_stage = [&](int kc, int s) {
        const uint32_t st = sbase + (uint32_t)s * STAGE;
        const size_t ko = (size_t)kc * 32;
        cpasync16(st + adst, Asrc + ko);
        cpasync16(st + bdst[0], Bs[0] + ko);
        cpasync16(st + bdst[1], Bs[1] + ko);
        cpasync16(st + bdst[2], Bs[2] + ko);
        asm volatile("cp.async.commit_group;" ::: "memory");
    };

    issue_stage(0, 0);
    issue_stage(1, 1);
    issue_stage(2, 2);

    for (int c = 0; c < NCH; c++) {
        asm volatile("cp.async.wait_group 2;" ::: "memory");
        __syncthreads();
        if (c + 3 < NCH) issue_stage(c + 3, (c + 3) & 3);

        const uint32_t st = sbase + (uint32_t)(c & 3) * STAGE;
#pragma unroll
        for (int ks = 0; ks < 2; ks++) {
            uint32_t ah[8], bb[12];
#pragma unroll
            for (int mt = 0; mt < 2; mt++) {
                const int row = wm + mt * 16 + (lid & 15);
                const int c16 = ks * 2 + (lid >> 4);
                ldsm4(ah + mt * 4, st + swz(row, c16));
            }
#pragma unroll
            for (int np = 0; np < 3; np++) {
                const int row = wn + np * 16 + (lid & 7) + ((lid >> 4) << 3);
                const int c16 = ks * 2 + ((lid >> 3) & 1);
                ldsm4(bb + np * 4, st + 4096 + swz(row, c16));
            }
#pragma unroll
            for (int mt = 0; mt < 2; mt++)
#pragma unroll
                for (int np = 0; np < 3; np++) {
                    mma_f16(acc[mt][np*2],     ah + mt*4, bb + np*4);
                    mma_f16(acc[mt][np*2 + 1], ah + mt*4, bb + np*4 + 2);
                }
        }
        __syncthreads();   // stage c fully consumed before refill
    }

    // epilogue: add bias, store fp32 into g_qkv[mat]
    const int tr = lid >> 2, tc = (lid & 3) * 2;
#pragma unroll
    for (int mt = 0; mt < 2; mt++)
#pragma unroll
        for (int n8 = 0; n8 < 6; n8++) {
            const int gn  = nb * 192 + wn + n8 * 8 + tc;
            const int mat = gn >> 7;
            const int col = gn & 127;
            const float* bias = (mat == 0) ? bq : (mat == 1) ? bk : bv;
            float* Cp = g_qkv[mat];
            const float b0 = bias[col], b1 = bias[col + 1];
            const int r0 = bm + wm + mt * 16 + tr;
            float2 v0 = {acc[mt][n8][0] + b0, acc[mt][n8][1] + b1};
            float2 v1 = {acc[mt][n8][2] + b0, acc[mt][n8][3] + b1};
            *(float2*)&Cp[(size_t)r0 * DH + col]       = v0;
            *(float2*)&Cp[(size_t)(r0 + 8) * DH + col] = v1;
        }
}

// ---------------- Kernel 2: kv partial reduction (16 chunks) ---------------
__global__ __launch_bounds__(256) void kv_reduce() {
    const int bh    = blockIdx.x;     // 0..63
    const int chunk = blockIdx.y;     // 0..15
    const int b = bh >> 3, h = bh & 7;
    const float* __restrict__ K = g_qkv[1];
    const float* __restrict__ V = g_qkv[2];

    const int l = chunk * 256 + threadIdx.x;
    const size_t base = (size_t)(b * Ll + l) * DH + h * Dd;
    float kx[Dd], vx[Dd], acc[Dd];
    const float4* kp = (const float4*)(K + base);
    const float4* vp = (const float4*)(V + base);
#pragma unroll
    for (int q = 0; q < 4; q++) {
        float4 kv4 = kp[q];
        kx[q*4+0] = kv4.x; kx[q*4+1] = kv4.y; kx[q*4+2] = kv4.z; kx[q*4+3] = kv4.w;
        float4 vv4 = vp[q];
        vx[q*4+0] = vv4.x; vx[q*4+1] = vv4.y; vx[q*4+2] = vv4.z; vx[q*4+3] = vv4.w;
    }
    float ss = 0.f;
#pragma unroll
    for (int d = 0; d < Dd; d++) ss += kx[d] * kx[d];
    const float rn = rsqrtf(ss);
#pragma unroll
    for (int d = 0; d < Dd; d++) acc[d] = kx[d] * rn * vx[d];

    __shared__ float red[256][17];
#pragma unroll
    for (int d = 0; d < Dd; d++) red[threadIdx.x][d] = acc[d];
    __syncthreads();
    for (int s = 128; s > 0; s >>= 1) {
        if (threadIdx.x < s) {
#pragma unroll
            for (int d = 0; d < Dd; d++)
                red[threadIdx.x][d] += red[threadIdx.x + s][d];
        }
        __syncthreads();
    }
    if (threadIdx.x < Dd)
        g_kvpart[bh][chunk][threadIdx.x] = red[0][threadIdx.x];
}

// ---------------- Kernel 3: q-normalize * kv, LayerNorm --------------------
__global__ __launch_bounds__(256) void finalize(
    const float* __restrict__ gamma, const float* __restrict__ beta,
    float* __restrict__ out)
{
    const int idx = blockIdx.x * blockDim.x + threadIdx.x;
    const int l = idx & (Ll - 1);
    const int h = (idx >> 12) & 7;
    const int b = idx >> 15;

    const size_t qbase = (size_t)(b * Ll + l) * DH + h * Dd;
    float q[Dd];
    const float4* qp = (const float4*)(g_qkv[0] + qbase);
#pragma unroll
    for (int g = 0; g < 4; g++) {
        float4 v = qp[g];
        q[g*4+0] = v.x; q[g*4+1] = v.y; q[g*4+2] = v.z; q[g*4+3] = v.w;
    }

    const int bh = (b << 3) | h;
    float kv[Dd];
#pragma unroll
    for (int d = 0; d < Dd; d++) kv[d] = 0.f;
#pragma unroll
    for (int c = 0; c < 16; c++)
#pragma unroll
        for (int d = 0; d < Dd; d++) kv[d] += g_kvpart[bh][c][d];

    float ss = 0.f;
#pragma unroll
    for (int d = 0; d < Dd; d++) ss += q[d] * q[d];
    const float rn = rsqrtf(ss);

    float a[Dd];
    float mu = 0.f;
#pragma unroll
    for (int d = 0; d < Dd; d++) { a[d] = q[d] * rn * kv[d]; mu += a[d]; }
    mu *= (1.f / Dd);
    float var = 0.f;
#pragma unroll
    for (int d = 0; d < Dd; d++) { float t = a[d] - mu; var += t * t; }
    var *= (1.f / Dd);
    const float rs = rsqrtf(var + 1e-5f);

    float* op = out + (size_t)idx * Dd;
#pragma unroll
    for (int g = 0; g < 4; g++) {
        float4 o;
        o.x = (a[g*4+0] - mu) * rs * gamma[g*4+0] + beta[g*4+0];
        o.y = (a[g*4+1] - mu) * rs * gamma[g*4+1] + beta[g*4+1];
        o.z = (a[g*4+2] - mu) * rs * gamma[g*4+2] + beta[g*4+2];
        o.w = (a[g*4+3] - mu) * rs * gamma[g*4+3] + beta[g*4+3];
        *(float4*)&op[g * 4] = o;
    }
}

// ---------------------------------------------------------------------------
extern "C" void kernel_launch(void* const* d_in, const int* in_sizes, int n_in,
                              void* d_out, int out_size)
{
    (void)in_sizes; (void)n_in; (void)out_size;
    const float* x     = (const float*)d_in[0];
    const float* Wq    = (const float*)d_in[1];
    const float* bq    = (const float*)d_in[2];
    const float* Wk    = (const float*)d_in[3];
    const float* bk    = (const float*)d_in[4];
    const float* Wv    = (const float*)d_in[5];
    const float* bv    = (const float*)d_in[6];
    const float* gamma = (const float*)d_in[7];
    const float* beta  = (const float*)d_in[8];
    float* out = (float*)d_out;

    static bool attr_set = false;
    if (!attr_set) {
        cudaFuncSetAttribute(qkv_gemm,
                             cudaFuncAttributeMaxDynamicSharedMemorySize, GEMM_SMEM);
        attr_set = true;
    }

    split_x<<<16384, 256>>>(x);
    split_w<<<192, 256>>>(Wq, Wk, Wv);
    qkv_gemm<<<dim3(2, 512), NTHR, GEMM_SMEM>>>(bq, bk, bv);
    kv_reduce<<<dim3(Bb * NH, 16), 256>>>();
    finalize<<<(Bb * NH * Ll) / 256, 256>>>(gamma, beta, out);
}

// round 15
// speedup vs baseline: 1.2304x; 1.0530x over previous
#include <cuda_runtime.h>
#include <cuda_fp16.h>
#include <cstdint>

// ---------------------------------------------------------------------------
// HydraAttention: B=8, L=4096, dim=1024, n_heads=8, d_head=128, d=16
// Round 15: fp16 pre-split + cp.async GEMM, 2 CTAs/SM, BK=64, 3x32KB stages
//   (16 iters, ONE barrier per iter, 48-HMMA bursts, SW128 full-width swizzle)
// ---------------------------------------------------------------------------

static constexpr int Bb  = 8;
static constexpr int Ll  = 4096;
static constexpr int DIM = 1024;
static constexpr int DH  = 128;
static constexpr int NH  = 8;
static constexpr int Dd  = 16;
static constexpr int MTOK = Bb * Ll;      // 32768

__device__ float g_qkv[3][MTOK * DH];     // 48 MB scratch
__device__ float g_kvpart[Bb * NH][16][Dd];
__device__ __align__(16) __half g_xf16[(size_t)MTOK * DIM];   // 64 MB
__device__ __align__(16) __half g_wf16[3 * DH * DIM];         // QKV concat

// ---------------- PTX helpers ----------------------------------------------
__device__ __forceinline__ uint32_t smem_u32(const void* p) {
    uint32_t a;
    asm("{ .reg .u64 t; cvta.to.shared.u64 t, %1; cvt.u32.u64 %0, t; }"
        : "=r"(a) : "l"(p));
    return a;
}
__device__ __forceinline__ void cpasync16(uint32_t dst, const void* src) {
    asm volatile("cp.async.cg.shared.global [%0], [%1], 16;" :: "r"(dst), "l"(src));
}
__device__ __forceinline__ void ldsm4(uint32_t* r, uint32_t a) {
    asm volatile("ldmatrix.sync.aligned.m8n8.x4.shared.b16 {%0,%1,%2,%3}, [%4];"
        : "=r"(r[0]), "=r"(r[1]), "=r"(r[2]), "=r"(r[3]) : "r"(a));
}
__device__ __forceinline__ void mma_f16(float* c, const uint32_t* a, const uint32_t* b) {
    asm volatile(
        "mma.sync.aligned.m16n8k16.row.col.f32.f16.f16.f32 "
        "{%0,%1,%2,%3}, {%4,%5,%6,%7}, {%8,%9}, {%0,%1,%2,%3};"
        : "+f"(c[0]), "+f"(c[1]), "+f"(c[2]), "+f"(c[3])
        : "r"(a[0]), "r"(a[1]), "r"(a[2]), "r"(a[3]), "r"(b[0]), "r"(b[1]));
}

// Full-width SW128 swizzle for 128B rows (BK=64 fp16): c16 in 0..7.
__device__ __forceinline__ uint32_t swz(int row, int c16) {
    return (uint32_t)(row * 128 + ((c16 ^ (row & 7)) << 4));
}

// ---------------- Kernel 0a: X fp32 -> fp16 --------------------------------
__global__ __launch_bounds__(256) void split_x(const float* __restrict__ X) {
    const size_t t = (size_t)blockIdx.x * 256 + threadIdx.x;   // 8 elems each
    const float4* p = (const float4*)(X + t * 8);
    float4 a = p[0], b = p[1];
    __align__(16) __half h[8];
    h[0] = __float2half_rn(a.x); h[1] = __float2half_rn(a.y);
    h[2] = __float2half_rn(a.z); h[3] = __float2half_rn(a.w);
    h[4] = __float2half_rn(b.x); h[5] = __float2half_rn(b.y);
    h[6] = __float2half_rn(b.z); h[7] = __float2half_rn(b.w);
    *(uint4*)(g_xf16 + t * 8) = *(const uint4*)h;
}

// ---------------- Kernel 0b: W fp32 -> fp16 (QKV concatenated) -------------
__global__ __launch_bounds__(256) void split_w(const float* __restrict__ Wq,
                                               const float* __restrict__ Wk,
                                               const float* __restrict__ Wv) {
    const size_t t = (size_t)blockIdx.x * 256 + threadIdx.x;
    const size_t e = t * 8;
    const int mat = (int)(e >> 17);
    const size_t off = e & 131071;
    const float* W = (mat == 0) ? Wq : (mat == 1) ? Wk : Wv;
    const float4* p = (const float4*)(W + off);
    float4 a = p[0], b = p[1];
    __align__(16) __half h[8];
    h[0] = __float2half_rn(a.x); h[1] = __float2half_rn(a.y);
    h[2] = __float2half_rn(a.z); h[3] = __float2half_rn(a.w);
    h[4] = __float2half_rn(b.x); h[5] = __float2half_rn(b.y);
    h[6] = __float2half_rn(b.z); h[7] = __float2half_rn(b.w);
    *(uint4*)(g_wf16 + e) = *(const uint4*)h;
}

// ---------------- Kernel 1: cp.async fp16 QKV GEMM, 2 CTAs/SM, BK=64 -------
// grid = (2, 512): N-half x M-block(64). Stage (32KB):
//   A[64x64] @0 (8KB), B[192x64] @8192 (24KB); 3 stages = 96KB
static constexpr uint32_t STAGE = 32768;
static constexpr int NSTG = 3;
static constexpr uint32_t GEMM_SMEM = NSTG * STAGE;   // 98304
static constexpr int NCH = 16;                        // K chunks of 64
static constexpr int NTHR = 256;

__global__ __launch_bounds__(NTHR, 2) void qkv_gemm(
    const float* __restrict__ bq, const float* __restrict__ bk,
    const float* __restrict__ bv)
{
    extern __shared__ __align__(128) unsigned char smem[];
    const uint32_t sbase = smem_u32(smem);
    const int tid = threadIdx.x, lid = tid & 31, wid = tid >> 5;
    const int nb = blockIdx.x;            // 0/1 -> QKV cols [nb*192, +192)
    const int bm = blockIdx.y * 64;
    const int wm = (wid >> 2) * 32;       // 2 M-warps x 32
    const int wn = (wid & 3) * 48;        // 4 N-warps x 48

    float acc[2][6][4];
#pragma unroll
    for (int i = 0; i < 2; i++)
#pragma unroll
        for (int j = 0; j < 6; j++)
#pragma unroll
            for (int k = 0; k < 4; k++) acc[i][j][k] = 0.f;

    // A: 64 rows x 8 slots = 512 -> 2/thread. B: 192 x 8 = 1536 -> 6/thread.
    const __half* As[2];
    uint32_t adst[2];
#pragma unroll
    for (int u = 0; u < 2; u++) {
        const int id = tid + NTHR * u;
        const int row = id >> 3, c16 = id & 7;
        As[u] = g_xf16 + (size_t)(bm + row) * DIM + c16 * 8;
        adst[u] = swz(row, c16);
    }
    const __half* Bs[6];
    uint32_t bdst[6];
#pragma unroll
    for (int u = 0; u < 6; u++) {
        const int id = tid + NTHR * u;
        const int row = id >> 3, c16 = id & 7;
        Bs[u] = g_wf16 + (size_t)(nb * 192 + row) * DIM + c16 * 8;
        bdst[u] = 8192 + swz(row, c16);
    }

    auto issue_stage = [&](int kc, int s) {
        const uint32_t st = sbase + (uint32_t)s * STAGE;
        const size_t ko = (size_t)kc * 64;
#pragma unroll
        for (int u = 0; u < 2; u++) cpasync16(st + adst[u], As[u] + ko);
#pragma unroll
        for (int u = 0; u < 6; u++) cpasync16(st + bdst[u], Bs[u] + ko);
        asm volatile("cp.async.commit_group;" ::: "memory");
    };

    issue_stage(0, 0);
    issue_stage(1, 1);

    for (int c = 0; c < NCH; c++) {
        asm volatile("cp.async.wait_group 1;" ::: "memory");
        __syncthreads();   // stage c data visible; stage (c+2)%3 fully consumed
        if (c + 2 < NCH) issue_stage(c + 2, (c + 2) % 3);

        const uint32_t st = sbase + (uint32_t)(c % 3) * STAGE;
#pragma unroll
        for (int ks = 0; ks < 4; ks++) {
            uint32_t ah[8], bb[12];
#pragma unroll
            for (int mt = 0; mt < 2; mt++) {
                const int row = wm + mt * 16 + (lid & 15);
                const int c16 = ks * 2 + (lid >> 4);
                ldsm4(ah + mt * 4, st + swz(row, c16));
            }
#pragma unroll
            for (int np = 0; np < 3; np++) {
                const int row = wn + np * 16 + (lid & 7) + ((lid >> 4) << 3);
                const int c16 = ks * 2 + ((lid >> 3) & 1);
                ldsm4(bb + np * 4, st + 8192 + swz(row, c16));
            }
#pragma unroll
            for (int mt = 0; mt < 2; mt++)
#pragma unroll
                for (int np = 0; np < 3; np++) {
                    mma_f16(acc[mt][np*2],     ah + mt*4, bb + np*4);
                    mma_f16(acc[mt][np*2 + 1], ah + mt*4, bb + np*4 + 2);
                }
        }
        // no end-of-loop barrier: next iteration's top sync orders stage reuse
    }

    // epilogue: add bias, store fp32 into g_qkv[mat]
    const int tr = lid >> 2, tc = (lid & 3) * 2;
#pragma unroll
    for (int mt = 0; mt < 2; mt++)
#pragma unroll
        for (int n8 = 0; n8 < 6; n8++) {
            const int gn  = nb * 192 + wn + n8 * 8 + tc;
            const int mat = gn >> 7;
            const int col = gn & 127;
            const float* bias = (mat == 0) ? bq : (mat == 1) ? bk : bv;
            float* Cp = g_qkv[mat];
            const float b0 = bias[col], b1 = bias[col + 1];
            const int r0 = bm + wm + mt * 16 + tr;
            float2 v0 = {acc[mt][n8][0] + b0, acc[mt][n8][1] + b1};
            float2 v1 = {acc[mt][n8][2] + b0, acc[mt][n8][3] + b1};
            *(float2*)&Cp[(size_t)r0 * DH + col]       = v0;
            *(float2*)&Cp[(size_t)(r0 + 8) * DH + col] = v1;
        }
}

// ---------------- Kernel 2: kv partial reduction (16 chunks) ---------------
__global__ __launch_bounds__(256) void kv_reduce() {
    const int bh    = blockIdx.x;     // 0..63
    const int chunk = blockIdx.y;     // 0..15
    const int b = bh >> 3, h = bh & 7;
    const float* __restrict__ K = g_qkv[1];
    const float* __restrict__ V = g_qkv[2];

    const int l = chunk * 256 + threadIdx.x;
    const size_t base = (size_t)(b * Ll + l) * DH + h * Dd;
    float kx[Dd], vx[Dd], acc[Dd];
    const float4* kp = (const float4*)(K + base);
    const float4* vp = (const float4*)(V + base);
#pragma unroll
    for (int q = 0; q < 4; q++) {
        float4 kv4 = kp[q];
        kx[q*4+0] = kv4.x; kx[q*4+1] = kv4.y; kx[q*4+2] = kv4.z; kx[q*4+3] = kv4.w;
        float4 vv4 = vp[q];
        vx[q*4+0] = vv4.x; vx[q*4+1] = vv4.y; vx[q*4+2] = vv4.z; vx[q*4+3] = vv4.w;
    }
    float ss = 0.f;
#pragma unroll
    for (int d = 0; d < Dd; d++) ss += kx[d] * kx[d];
    const float rn = rsqrtf(ss);
#pragma unroll
    for (int d = 0; d < Dd; d++) acc[d] = kx[d] * rn * vx[d];

    __shared__ float red[256][17];
#pragma unroll
    for (int d = 0; d < Dd; d++) red[threadIdx.x][d] = acc[d];
    __syncthreads();
    for (int s = 128; s > 0; s >>= 1) {
        if (threadIdx.x < s) {
#pragma unroll
            for (int d = 0; d < Dd; d++)
                red[threadIdx.x][d] += red[threadIdx.x + s][d];
        }
        __syncthreads();
    }
    if (threadIdx.x < Dd)
        g_kvpart[bh][chunk][threadIdx.x] = red[0][threadIdx.x];
}

// ---------------- Kernel 3: q-normalize * kv, LayerNorm --------------------
__global__ __launch_bounds__(256) void finalize(
    const float* __restrict__ gamma, const float* __restrict__ beta,
    float* __restrict__ out)
{
    const int idx = blockIdx.x * blockDim.x + threadIdx.x;
    const int l = idx & (Ll - 1);
    const int h = (idx >> 12) & 7;
    const int b = idx >> 15;

    const size_t qbase = (size_t)(b * Ll + l) * DH + h * Dd;
    float q[Dd];
    const float4* qp = (const float4*)(g_qkv[0] + qbase);
#pragma unroll
    for (int g = 0; g < 4; g++) {
        float4 v = qp[g];
        q[g*4+0] = v.x; q[g*4+1] = v.y; q[g*4+2] = v.z; q[g*4+3] = v.w;
    }

    const int bh = (b << 3) | h;
    float kv[Dd];
#pragma unroll
    for (int d = 0; d < Dd; d++) kv[d] = 0.f;
#pragma unroll
    for (int c = 0; c < 16; c++)
#pragma unroll
        for (int d = 0; d < Dd; d++) kv[d] += g_kvpart[bh][c][d];

    float ss = 0.f;
#pragma unroll
    for (int d = 0; d < Dd; d++) ss += q[d] * q[d];
    const float rn = rsqrtf(ss);

    float a[Dd];
    float mu = 0.f;
#pragma unroll
    for (int d = 0; d < Dd; d++) { a[d] = q[d] * rn * kv[d]; mu += a[d]; }
    mu *= (1.f / Dd);
    float var = 0.f;
#pragma unroll
    for (int d = 0; d < Dd; d++) { float t = a[d] - mu; var += t * t; }
    var *= (1.f / Dd);
    const float rs = rsqrtf(var + 1e-5f);

    float* op = out + (size_t)idx * Dd;
#pragma unroll
    for (int g = 0; g < 4; g++) {
        float4 o;
        o.x = (a[g*4+0] - mu) * rs * gamma[g*4+0] + beta[g*4+0];
        o.y = (a[g*4+1] - mu) * rs * gamma[g*4+1] + beta[g*4+1];
        o.z = (a[g*4+2] - mu) * rs * gamma[g*4+2] + beta[g*4+2];
        o.w = (a[g*4+3] - mu) * rs * gamma[g*4+3] + beta[g*4+3];
        *(float4*)&op[g * 4] = o;
    }
}

// ---------------------------------------------------------------------------
extern "C" void kernel_launch(void* const* d_in, const int* in_sizes, int n_in,
                              void* d_out, int out_size)
{
    (void)in_sizes; (void)n_in; (void)out_size;
    const float* x     = (const float*)d_in[0];
    const float* Wq    = (const float*)d_in[1];
    const float* bq    = (const float*)d_in[2];
    const float* Wk    = (const float*)d_in[3];
    const float* bk    = (const float*)d_in[4];
    const float* Wv    = (const float*)d_in[5];
    const float* bv    = (const float*)d_in[6];
    const float* gamma = (const float*)d_in[7];
    const float* beta  = (const float*)d_in[8];
    float* out = (float*)d_out;

    static bool attr_set = false;
    if (!attr_set) {
        cudaFuncSetAttribute(qkv_gemm,
                             cudaFuncAttributeMaxDynamicSharedMemorySize, GEMM_SMEM);
        attr_set = true;
    }

    split_x<<<16384, 256>>>(x);
    split_w<<<192, 256>>>(Wq, Wk, Wv);
    qkv_gemm<<<dim3(2, 512), NTHR, GEMM_SMEM>>>(bq, bk, bv);
    kv_reduce<<<dim3(Bb * NH, 16), 256>>>();
    finalize<<<(Bb * NH * Ll) / 256, 256>>>(gamma, beta, out);
}

// round 16
// speedup vs baseline: 1.2835x; 1.0431x over previous
#include <cuda_runtime.h>
#include <cuda_fp16.h>
#include <cstdint>

// ---------------------------------------------------------------------------
// HydraAttention: B=8, L=4096, dim=1024, n_heads=8, d_head=128, d=16
// Round 16: R15 GEMM + HEAD-MAJOR Q/K/V layout [bh][l][16] so kv_reduce /
//           finalize stream fully coalesced (they were at 25% of HBM peak)
// ---------------------------------------------------------------------------

static constexpr int Bb  = 8;
static constexpr int Ll  = 4096;
static constexpr int DIM = 1024;
static constexpr int DH  = 128;
static constexpr int NH  = 8;
static constexpr int Dd  = 16;
static constexpr int MTOK = Bb * Ll;      // 32768

// head-major: [mat][bh*4096 + l][16]
__device__ float g_qkv[3][(size_t)Bb * NH * Ll * Dd];
__device__ float g_kvpart[Bb * NH][16][Dd];
__device__ __align__(16) __half g_xf16[(size_t)MTOK * DIM];   // 64 MB
__device__ __align__(16) __half g_wf16[3 * DH * DIM];         // QKV concat

// ---------------- PTX helpers ----------------------------------------------
__device__ __forceinline__ uint32_t smem_u32(const void* p) {
    uint32_t a;
    asm("{ .reg .u64 t; cvta.to.shared.u64 t, %1; cvt.u32.u64 %0, t; }"
        : "=r"(a) : "l"(p));
    return a;
}
__device__ __forceinline__ void cpasync16(uint32_t dst, const void* src) {
    asm volatile("cp.async.cg.shared.global [%0], [%1], 16;" :: "r"(dst), "l"(src));
}
__device__ __forceinline__ void ldsm4(uint32_t* r, uint32_t a) {
    asm volatile("ldmatrix.sync.aligned.m8n8.x4.shared.b16 {%0,%1,%2,%3}, [%4];"
        : "=r"(r[0]), "=r"(r[1]), "=r"(r[2]), "=r"(r[3]) : "r"(a));
}
__device__ __forceinline__ void mma_f16(float* c, const uint32_t* a, const uint32_t* b) {
    asm volatile(
        "mma.sync.aligned.m16n8k16.row.col.f32.f16.f16.f32 "
        "{%0,%1,%2,%3}, {%4,%5,%6,%7}, {%8,%9}, {%0,%1,%2,%3};"
        : "+f"(c[0]), "+f"(c[1]), "+f"(c[2]), "+f"(c[3])
        : "r"(a[0]), "r"(a[1]), "r"(a[2]), "r"(a[3]), "r"(b[0]), "r"(b[1]));
}

// Full-width SW128 swizzle for 128B rows (BK=64 fp16): c16 in 0..7.
__device__ __forceinline__ uint32_t swz(int row, int c16) {
    return (uint32_t)(row * 128 + ((c16 ^ (row & 7)) << 4));
}

// ---------------- Kernel 0a: X fp32 -> fp16 --------------------------------
__global__ __launch_bounds__(256) void split_x(const float* __restrict__ X) {
    const size_t t = (size_t)blockIdx.x * 256 + threadIdx.x;   // 8 elems each
    const float4* p = (const float4*)(X + t * 8);
    float4 a = p[0], b = p[1];
    __align__(16) __half h[8];
    h[0] = __float2half_rn(a.x); h[1] = __float2half_rn(a.y);
    h[2] = __float2half_rn(a.z); h[3] = __float2half_rn(a.w);
    h[4] = __float2half_rn(b.x); h[5] = __float2half_rn(b.y);
    h[6] = __float2half_rn(b.z); h[7] = __float2half_rn(b.w);
    *(uint4*)(g_xf16 + t * 8) = *(const uint4*)h;
}

// ---------------- Kernel 0b: W fp32 -> fp16 (QKV concatenated) -------------
__global__ __launch_bounds__(256) void split_w(const float* __restrict__ Wq,
                                               const float* __restrict__ Wk,
                                               const float* __restrict__ Wv) {
    const size_t t = (size_t)blockIdx.x * 256 + threadIdx.x;
    const size_t e = t * 8;
    const int mat = (int)(e >> 17);
    const size_t off = e & 131071;
    const float* W = (mat == 0) ? Wq : (mat == 1) ? Wk : Wv;
    const float4* p = (const float4*)(W + off);
    float4 a = p[0], b = p[1];
    __align__(16) __half h[8];
    h[0] = __float2half_rn(a.x); h[1] = __float2half_rn(a.y);
    h[2] = __float2half_rn(a.z); h[3] = __float2half_rn(a.w);
    h[4] = __float2half_rn(b.x); h[5] = __float2half_rn(b.y);
    h[6] = __float2half_rn(b.z); h[7] = __float2half_rn(b.w);
    *(uint4*)(g_wf16 + e) = *(const uint4*)h;
}

// ---------------- Kernel 1: cp.async fp16 QKV GEMM, 2 CTAs/SM, BK=64 -------
// grid = (2, 512): N-half x M-block(64). Stage (32KB):
//   A[64x64] @0 (8KB), B[192x64] @8192 (24KB); 3 stages = 96KB
static constexpr uint32_t STAGE = 32768;
static constexpr int NSTG = 3;
static constexpr uint32_t GEMM_SMEM = NSTG * STAGE;   // 98304
static constexpr int NCH = 16;                        // K chunks of 64
static constexpr int NTHR = 256;

__global__ __launch_bounds__(NTHR, 2) void qkv_gemm(
    const float* __restrict__ bq, const float* __restrict__ bk,
    const float* __restrict__ bv)
{
    extern __shared__ __align__(128) unsigned char smem[];
    const uint32_t sbase = smem_u32(smem);
    const int tid = threadIdx.x, lid = tid & 31, wid = tid >> 5;
    const int nb = blockIdx.x;            // 0/1 -> QKV cols [nb*192, +192)
    const int bm = blockIdx.y * 64;
    const int wm = (wid >> 2) * 32;       // 2 M-warps x 32
    const int wn = (wid & 3) * 48;        // 4 N-warps x 48

    float acc[2][6][4];
#pragma unroll
    for (int i = 0; i < 2; i++)
#pragma unroll
        for (int j = 0; j < 6; j++)
#pragma unroll
            for (int k = 0; k < 4; k++) acc[i][j][k] = 0.f;

    // A: 64 rows x 8 slots = 512 -> 2/thread. B: 192 x 8 = 1536 -> 6/thread.
    const __half* As[2];
    uint32_t adst[2];
#pragma unroll
    for (int u = 0; u < 2; u++) {
        const int id = tid + NTHR * u;
        const int row = id >> 3, c16 = id & 7;
        As[u] = g_xf16 + (size_t)(bm + row) * DIM + c16 * 8;
        adst[u] = swz(row, c16);
    }
    const __half* Bs[6];
    uint32_t bdst[6];
#pragma unroll
    for (int u = 0; u < 6; u++) {
        const int id = tid + NTHR * u;
        const int row = id >> 3, c16 = id & 7;
        Bs[u] = g_wf16 + (size_t)(nb * 192 + row) * DIM + c16 * 8;
        bdst[u] = 8192 + swz(row, c16);
    }

    auto issue_stage = [&](int kc, int s) {
        const uint32_t st = sbase + (uint32_t)s * STAGE;
        const size_t ko = (size_t)kc * 64;
#pragma unroll
        for (int u = 0; u < 2; u++) cpasync16(st + adst[u], As[u] + ko);
#pragma unroll
        for (int u = 0; u < 6; u++) cpasync16(st + bdst[u], Bs[u] + ko);
        asm volatile("cp.async.commit_group;" ::: "memory");
    };

    issue_stage(0, 0);
    issue_stage(1, 1);

    for (int c = 0; c < NCH; c++) {
        asm volatile("cp.async.wait_group 1;" ::: "memory");
        __syncthreads();   // stage c visible; stage (c+2)%3 fully consumed
        if (c + 2 < NCH) issue_stage(c + 2, (c + 2) % 3);

        const uint32_t st = sbase + (uint32_t)(c % 3) * STAGE;
#pragma unroll
        for (int ks = 0; ks < 4; ks++) {
            uint32_t ah[8], bb[12];
#pragma unroll
            for (int mt = 0; mt < 2; mt++) {
                const int row = wm + mt * 16 + (lid & 15);
                const int c16 = ks * 2 + (lid >> 4);
                ldsm4(ah + mt * 4, st + swz(row, c16));
            }
#pragma unroll
            for (int np = 0; np < 3; np++) {
                const int row = wn + np * 16 + (lid & 7) + ((lid >> 4) << 3);
                const int c16 = ks * 2 + ((lid >> 3) & 1);
                ldsm4(bb + np * 4, st + 8192 + swz(row, c16));
            }
#pragma unroll
            for (int mt = 0; mt < 2; mt++)
#pragma unroll
                for (int np = 0; np < 3; np++) {
                    mma_f16(acc[mt][np*2],     ah + mt*4, bb + np*4);
                    mma_f16(acc[mt][np*2 + 1], ah + mt*4, bb + np*4 + 2);
                }
        }
    }

    // epilogue: add bias, store fp32 HEAD-MAJOR: g_qkv[mat][(b*8+h)*4096+l][16]
    const int tr = lid >> 2, tc = (lid & 3) * 2;
#pragma unroll
    for (int mt = 0; mt < 2; mt++)
#pragma unroll
        for (int n8 = 0; n8 < 6; n8++) {
            const int gn  = nb * 192 + wn + n8 * 8 + tc;   // 0..383
            const int mat = gn >> 7;
            const int col = gn & 127;                      // col in d_head
            const int h   = col >> 4;                      // head
            const int d0  = col & 15;                      // dim (even)
            const float* bias = (mat == 0) ? bq : (mat == 1) ? bk : bv;
            float* Cp = g_qkv[mat];
            const float b0 = bias[col], b1 = bias[col + 1];
            const int r0 = bm + wm + mt * 16 + tr;         // token 0..32767
            const int r1 = r0 + 8;
            const int bb0 = (r0 >> 12), l0 = r0 & 4095;
            const int bb1 = (r1 >> 12), l1 = r1 & 4095;
            float2 v0 = {acc[mt][n8][0] + b0, acc[mt][n8][1] + b1};
            float2 v1 = {acc[mt][n8][2] + b0, acc[mt][n8][3] + b1};
            *(float2*)&Cp[((size_t)((bb0 * 8 + h) * 4096 + l0)) * Dd + d0] = v0;
            *(float2*)&Cp[((size_t)((bb1 * 8 + h) * 4096 + l1)) * Dd + d0] = v1;
        }
}

// ---------------- Kernel 2: kv partial reduction (coalesced) ---------------
__global__ __launch_bounds__(256) void kv_reduce() {
    const int bh    = blockIdx.x;     // 0..63
    const int chunk = blockIdx.y;     // 0..15
    const float* __restrict__ K = g_qkv[1];
    const float* __restrict__ V = g_qkv[2];

    const int l = chunk * 256 + threadIdx.x;
    const size_t base = ((size_t)bh * Ll + l) * Dd;      // contiguous 64B rows
    float kx[Dd], vx[Dd], acc[Dd];
    const float4* kp = (const float4*)(K + base);
    const float4* vp = (const float4*)(V + base);
#pragma unroll
    for (int q = 0; q < 4; q++) {
        float4 kv4 = kp[q];
        kx[q*4+0] = kv4.x; kx[q*4+1] = kv4.y; kx[q*4+2] = kv4.z; kx[q*4+3] = kv4.w;
        float4 vv4 = vp[q];
        vx[q*4+0] = vv4.x; vx[q*4+1] = vv4.y; vx[q*4+2] = vv4.z; vx[q*4+3] = vv4.w;
    }
    float ss = 0.f;
#pragma unroll
    for (int d = 0; d < Dd; d++) ss += kx[d] * kx[d];
    const float rn = rsqrtf(ss);
#pragma unroll
    for (int d = 0; d < Dd; d++) acc[d] = kx[d] * rn * vx[d];

    __shared__ float red[256][17];
#pragma unroll
    for (int d = 0; d < Dd; d++) red[threadIdx.x][d] = acc[d];
    __syncthreads();
    for (int s = 128; s > 0; s >>= 1) {
        if (threadIdx.x < s) {
#pragma unroll
            for (int d = 0; d < Dd; d++)
                red[threadIdx.x][d] += red[threadIdx.x + s][d];
        }
        __syncthreads();
    }
    if (threadIdx.x < Dd)
        g_kvpart[bh][chunk][threadIdx.x] = red[0][threadIdx.x];
}

// ---------------- Kernel 3: q-normalize * kv, LayerNorm --------------------
__global__ __launch_bounds__(256) void finalize(
    const float* __restrict__ gamma, const float* __restrict__ beta,
    float* __restrict__ out)
{
    const int idx = blockIdx.x * blockDim.x + threadIdx.x;   // bh*4096 + l
    const int bh = idx >> 12;

    const size_t base = (size_t)idx * Dd;                    // contiguous
    float q[Dd];
    const float4* qp = (const float4*)(g_qkv[0] + base);
#pragma unroll
    for (int g = 0; g < 4; g++) {
        float4 v = qp[g];
        q[g*4+0] = v.x; q[g*4+1] = v.y; q[g*4+2] = v.z; q[g*4+3] = v.w;
    }

    float kv[Dd];
#pragma unroll
    for (int d = 0; d < Dd; d++) kv[d] = 0.f;
#pragma unroll
    for (int c = 0; c < 16; c++)
#pragma unroll
        for (int d = 0; d < Dd; d++) kv[d] += g_kvpart[bh][c][d];

    float ss = 0.f;
#pragma unroll
    for (int d = 0; d < Dd; d++) ss += q[d] * q[d];
    const float rn = rsqrtf(ss);

    float a[Dd];
    float mu = 0.f;
#pragma unroll
    for (int d = 0; d < Dd; d++) { a[d] = q[d] * rn * kv[d]; mu += a[d]; }
    mu *= (1.f / Dd);
    float var = 0.f;
#pragma unroll
    for (int d = 0; d < Dd; d++) { float t = a[d] - mu; var += t * t; }
    var *= (1.f / Dd);
    const float rs = rsqrtf(var + 1e-5f);

    // out is [B, nh, L, d] == head-major linear: same index
    float* op = out + base;
#pragma unroll
    for (int g = 0; g < 4; g++) {
        float4 o;
        o.x = (a[g*4+0] - mu) * rs * gamma[g*4+0] + beta[g*4+0];
        o.y = (a[g*4+1] - mu) * rs * gamma[g*4+1] + beta[g*4+1];
        o.z = (a[g*4+2] - mu) * rs * gamma[g*4+2] + beta[g*4+2];
        o.w = (a[g*4+3] - mu) * rs * gamma[g*4+3] + beta[g*4+3];
        *(float4*)&op[g * 4] = o;
    }
}

// ---------------------------------------------------------------------------
extern "C" void kernel_launch(void* const* d_in, const int* in_sizes, int n_in,
                              void* d_out, int out_size)
{
    (void)in_sizes; (void)n_in; (void)out_size;
    const float* x     = (const float*)d_in[0];
    const float* Wq    = (const float*)d_in[1];
    const float* bq    = (const float*)d_in[2];
    const float* Wk    = (const float*)d_in[3];
    const float* bk    = (const float*)d_in[4];
    const float* Wv    = (const float*)d_in[5];
    const float* bv    = (const float*)d_in[6];
    const float* gamma = (const float*)d_in[7];
    const float* beta  = (const float*)d_in[8];
    float* out = (float*)d_out;

    static bool attr_set = false;
    if (!attr_set) {
        cudaFuncSetAttribute(qkv_gemm,
                             cudaFuncAttributeMaxDynamicSharedMemorySize, GEMM_SMEM);
        attr_set = true;
    }

    split_x<<<16384, 256>>>(x);
    split_w<<<192, 256>>>(Wq, Wk, Wv);
    qkv_gemm<<<dim3(2, 512), NTHR, GEMM_SMEM>>>(bq, bk, bv);
    kv_reduce<<<dim3(Bb * NH, 16), 256>>>();
    finalize<<<(Bb * NH * Ll) / 256, 256>>>(gamma, beta, out);
}